// round 2
// baseline (speedup 1.0000x reference)
#include <cuda_runtime.h>
#include <cuda_bf16.h>

#define EPS 1e-6f
#define TW 32   // output tile width per block
#define TH 32   // output tile height per block
// input tile loaded: (TH+1) x (TW+1) = 33 x 33

__global__ __launch_bounds__(256, 8)
void entropy2x2_kernel(const float* __restrict__ x, float* __restrict__ out)
{
    // +padding column (stride 34) keeps consecutive-lane smem reads conflict-free
    __shared__ float Xs[TH + 1][TW + 2];
    __shared__ float Ls[TH + 1][TW + 2];

    const int plane = blockIdx.z;          // 0..511  (b*c planes)
    const int x0 = blockIdx.x * TW;
    const int y0 = blockIdx.y * TH;

    const float* __restrict__ px = x + (size_t)plane * (256 * 256);
    float*       __restrict__ po = out + (size_t)plane * (255 * 255);

    const int t = threadIdx.x;

    // Cooperative load of 33x33 halo tile; fuse per-pixel w*log(w+eps).
    // 1089 elems / 256 threads -> ~5 independent LDGs in flight per thread.
    #pragma unroll
    for (int idx = t; idx < 33 * 33; idx += 256) {
        int r = idx / 33;
        int c = idx - r * 33;
        int gr = y0 + r;
        int gc = x0 + c;
        float v = 0.0f;
        if (gr < 256 && gc < 256) v = px[gr * 256 + gc];
        Xs[r][c] = v;
        Ls[r][c] = v * __logf(v + EPS);   // exactly one log per pixel
    }
    __syncthreads();

    const int tx  = t & 31;      // output col within tile
    const int ty0 = t >> 5;      // 0..7; each thread does 4 rows (stride 8)

    #pragma unroll
    for (int k = 0; k < 4; k++) {
        const int oy = ty0 + k * 8;
        const int gy = y0 + oy;
        const int gx = x0 + tx;
        if (gy < 255 && gx < 255) {
            float s  = (Xs[oy][tx]   + Xs[oy][tx + 1])
                     + (Xs[oy + 1][tx] + Xs[oy + 1][tx + 1]);
            float sl = (Ls[oy][tx]   + Ls[oy][tx + 1])
                     + (Ls[oy + 1][tx] + Ls[oy + 1][tx + 1]);
            float S   = s + EPS;
            float inv = __frcp_rn(S);
            // ent = (s/S)*log(S) - (1/S)*sum(w*log(w+eps))
            float ent = inv * (s * __logf(S) - sl);
            po[gy * 255 + gx] = ent;
        }
    }
}

extern "C" void kernel_launch(void* const* d_in, const int* in_sizes, int n_in,
                              void* d_out, int out_size)
{
    const float* x = (const float*)d_in[0];
    float* out = (float*)d_out;

    // planes = 8*64 = 512; per-plane output 255x255 -> 8x8 tiles of 32x32
    dim3 grid((255 + TW - 1) / TW, (255 + TH - 1) / TH, 512);
    entropy2x2_kernel<<<grid, 256>>>(x, out);
}

// round 3
// speedup vs baseline: 1.2798x; 1.2798x over previous
#include <cuda_runtime.h>
#include <cuda_bf16.h>

#define EPS 1e-6f
#define RROWS 16   // output rows per thread

__device__ __forceinline__ float fast_rcp(float a) {
    float r;
    asm("rcp.approx.f32 %0, %1;" : "=f"(r) : "f"(a));
    return r;
}

// Per-row: load 5 pixels (float4 + scalar), produce horizontal pair sums of
// v and of L = v*log(v+eps). 4 h-values each, reused by two output rows.
__device__ __forceinline__ void load_row(const float* __restrict__ rp, bool lastcol,
                                         float hv[4], float hl[4])
{
    float4 v4 = *reinterpret_cast<const float4*>(rp);
    float  v5 = lastcol ? 0.0f : rp[4];

    float l0 = v4.x * __logf(v4.x + EPS);
    float l1 = v4.y * __logf(v4.y + EPS);
    float l2 = v4.z * __logf(v4.z + EPS);
    float l3 = v4.w * __logf(v4.w + EPS);
    float l4 = v5   * __logf(v5   + EPS);

    hv[0] = v4.x + v4.y;  hv[1] = v4.y + v4.z;
    hv[2] = v4.z + v4.w;  hv[3] = v4.w + v5;
    hl[0] = l0 + l1;      hl[1] = l1 + l2;
    hl[2] = l2 + l3;      hl[3] = l3 + l4;
}

__global__ __launch_bounds__(256)
void entropy2x2_reg_kernel(const float* __restrict__ x, float* __restrict__ out)
{
    const int tx    = threadIdx.x;              // 0..63 -> column strip
    const int ty    = threadIdx.y;              // 0..3  -> row strip within block
    const int plane = blockIdx.z;               // 0..511
    const int c0    = tx * 4;                   // input/output col base
    const int yBase = blockIdx.y * (4 * RROWS) + ty * RROWS;

    const float* __restrict__ px = x   + (size_t)plane * (256 * 256) + c0;
    float*       __restrict__ po = out + (size_t)plane * (255 * 255) + (size_t)yBase * 255 + c0;

    const bool lastcol = (c0 == 252);           // col 256 would be OOB

    float hv_p[4], hl_p[4];
    load_row(px + yBase * 256, lastcol, hv_p, hl_p);

    #pragma unroll 4
    for (int r = 0; r < RROWS; r++) {
        const int gy = yBase + r;
        if (gy >= 255) break;                   // only trims the last row-block

        float hv_c[4], hl_c[4];
        load_row(px + (gy + 1) * 256, lastcol, hv_c, hl_c);

        #pragma unroll
        for (int i = 0; i < 4; i++) {
            float s    = hv_p[i] + hv_c[i];
            float sl   = hl_p[i] + hl_c[i];
            float S    = s + EPS;
            float logS = __logf(S);
            // ent = (s*log(S) - sum w*log(w+eps)) / S
            float ent  = fmaf(s, logS, -sl) * fast_rcp(S);
            if (c0 + i < 255)                   // only lastcol's i==3 is invalid
                po[i] = ent;
        }

        #pragma unroll
        for (int i = 0; i < 4; i++) { hv_p[i] = hv_c[i]; hl_p[i] = hl_c[i]; }
        po += 255;
    }
}

extern "C" void kernel_launch(void* const* d_in, const int* in_sizes, int n_in,
                              void* d_out, int out_size)
{
    const float* x = (const float*)d_in[0];
    float* out = (float*)d_out;

    // 64 column-strips of width 4 cover 255 output cols (last strip 3 valid).
    // grid.y * 4 * RROWS = 256 rows covers 255 output rows.
    dim3 block(64, 4);
    dim3 grid(1, 4, 512);
    entropy2x2_reg_kernel<<<grid, block>>>(x, out);
}